// round 14
// baseline (speedup 1.0000x reference)
#include <cuda_runtime.h>
#include <cuda_fp16.h>
#include <math.h>
#include <float.h>

#define NMAX 20000
#define NPAD 20128      // NMAX rounded up past 157*128, removes GEMM bound checks
#define EMAX 320000

// ---------------- device scratch (static, no allocations) ----------------
__device__ __half g_h[NPAD * 512];      // GEMM outputs (gather input), fp16
__device__ __half g_x[NPAD * 512];      // gather outputs (GEMM A / BN / pool input), fp16
__device__ float  g_als[NPAD * 8];
__device__ float  g_ald[NPAD * 8];
__device__ int    g_counts[NMAX];
__device__ int    g_offs[NMAX];
__device__ int    g_row_ptr[NMAX + 1];
__device__ int    g_col[EMAX];
__device__ float2 g_bn_part[128][512];
__device__ float  g_bn_scale[512];
__device__ float  g_bn_shift[512];
__device__ unsigned g_pmax[16 * 512];   // ordered-uint encoded raw max per (graph, ch)
__device__ unsigned g_pmin[16 * 512];   // ordered-uint encoded raw min per (graph, ch)

__device__ __forceinline__ unsigned h2u(__half2 h) {
    return *reinterpret_cast<unsigned*>(&h);
}
__device__ __forceinline__ unsigned f2tf32(float f) {
    unsigned u;
    asm("cvt.rna.tf32.f32 %0, %1;" : "=r"(u) : "f"(f));
    return u;
}
// monotonic float <-> unsigned encode (for atomicMax/Min on floats of any sign)
__device__ __forceinline__ unsigned f2o(float f) {
    unsigned u = __float_as_uint(f);
    return (u & 0x80000000u) ? ~u : (u | 0x80000000u);
}
__device__ __forceinline__ float o2f(unsigned e) {
    return (e & 0x80000000u) ? __uint_as_float(e ^ 0x80000000u)
                             : __uint_as_float(~e);
}

// ---------------- small utility kernels ----------------
__global__ void zero_init(int Nn) {
    int i = blockIdx.x * blockDim.x + threadIdx.x;
    if (i < Nn) g_counts[i] = 0;
    if (i < 16 * 512) {
        g_pmax[i] = 0u;            // identity for unsigned max
        g_pmin[i] = 0xFFFFFFFFu;   // identity for unsigned min
    }
}

__global__ void hist_kernel(const int* __restrict__ ei, int E) {
    int e = blockIdx.x * blockDim.x + threadIdx.x;
    if (e < E) atomicAdd(&g_counts[ei[E + e]], 1);
}

__global__ void scan_kernel(int Nn) {
    __shared__ int sh[1024];
    int tid = threadIdx.x;
    int per = (Nn + 1023) / 1024;
    int start = tid * per;
    int s = 0;
    for (int i = 0; i < per; i++) {
        int idx = start + i;
        if (idx < Nn) s += g_counts[idx];
    }
    sh[tid] = s;
    __syncthreads();
    for (int off = 1; off < 1024; off <<= 1) {
        int v = 0;
        if (tid >= off) v = sh[tid - off];
        __syncthreads();
        sh[tid] += v;
        __syncthreads();
    }
    int run = sh[tid] - s;  // exclusive
    for (int i = 0; i < per; i++) {
        int idx = start + i;
        if (idx < Nn) {
            g_row_ptr[idx] = run;
            g_offs[idx] = run;
            run += g_counts[idx];
        }
    }
    if (tid == 1023) g_row_ptr[Nn] = sh[1023];
}

__global__ void scatter_kernel(const int* __restrict__ ei, int E) {
    int e = blockIdx.x * blockDim.x + threadIdx.x;
    if (e < E) {
        int s = ei[e];
        int d = ei[E + e];
        int pos = atomicAdd(&g_offs[d], 1);
        g_col[pos] = s;
    }
}

// ---------------- layer-1: GEMM (K=3) fused with attention projections ----------------
__global__ __launch_bounds__(128) void gemm_l1_fused(const float* __restrict__ x,
                                                     const float* __restrict__ W,
                                                     const float* __restrict__ a_s,
                                                     const float* __restrict__ a_d,
                                                     __half* __restrict__ outp, int Nn) {
    int warp = threadIdx.x >> 5;
    int lane = threadIdx.x & 31;
    int n = blockIdx.x * 4 + warp;
    if (n >= Nn) return;
    float x0 = x[n * 3 + 0], x1 = x[n * 3 + 1], x2 = x[n * 3 + 2];
    int c = lane * 4;
    float4 w0 = *(const float4*)&W[c];
    float4 w1 = *(const float4*)&W[128 + c];
    float4 w2 = *(const float4*)&W[256 + c];
    float4 v;
    v.x = x0 * w0.x + x1 * w1.x + x2 * w2.x;
    v.y = x0 * w0.y + x1 * w1.y + x2 * w2.y;
    v.z = x0 * w0.z + x1 * w1.z + x2 * w2.z;
    v.w = x0 * w0.w + x1 * w1.w + x2 * w2.w;
    __half2 p0 = __floats2half2_rn(v.x, v.y);
    __half2 p1 = __floats2half2_rn(v.z, v.w);
    *(uint2*)&outp[(size_t)n * 128 + c] = make_uint2(h2u(p0), h2u(p1));
    float4 s4 = *(const float4*)&a_s[c];
    float4 d4 = *(const float4*)&a_d[c];
    float ps = v.x * s4.x + v.y * s4.y + v.z * s4.z + v.w * s4.w;
    float pd = v.x * d4.x + v.y * d4.y + v.z * d4.z + v.w * d4.w;
    ps += __shfl_xor_sync(0xffffffffu, ps, 2);
    ps += __shfl_xor_sync(0xffffffffu, ps, 1);
    pd += __shfl_xor_sync(0xffffffffu, pd, 2);
    pd += __shfl_xor_sync(0xffffffffu, pd, 1);
    if ((lane & 3) == 0) {
        int hh = lane >> 2;
        g_als[n * 8 + hh] = ps;
        g_ald[n * 8 + hh] = pd;
    }
}

// ---------------- pipelined tf32 tensor-core GEMM: C(fp16) = relu(BN(A(fp16))) @ B ---
template <int CH>
__global__ __launch_bounds__(256, 2) void gemm_tf32(const __half* __restrict__ A,
                                                    const float* __restrict__ B,
                                                    __half* __restrict__ Cc,
                                                    const float* __restrict__ a_s,
                                                    const float* __restrict__ a_d,
                                                    int N, int K) {
    __shared__ unsigned As[16][136];   // [k][m], tf32 bits
    __shared__ unsigned Bs[16][136];   // [k][n], tf32 bits
    int tid = threadIdx.x;
    int bx = blockIdx.x, by = blockIdx.y;
    int lane = tid & 31;
    int g = lane >> 2;         // groupID (0..7)
    int tig = lane & 3;        // thread in group (0..3)
    int warp = tid >> 5;
    int wm = (warp & 3) * 32;  // warp M offset within block tile
    int wn = (warp >> 2) * 64; // warp N offset within block tile

    float c[2][8][4];
#pragma unroll
    for (int mi = 0; mi < 2; mi++)
#pragma unroll
        for (int nj = 0; nj < 8; nj++)
#pragma unroll
            for (int q = 0; q < 4; q++) c[mi][nj][q] = 0.f;

    int a_row0 = tid >> 2;          // 0..63
    int a_col = (tid & 3) << 2;     // 0,4,8,12
    int b_row0 = tid >> 5;          // 0..7
    int b_col = (tid & 31) << 2;    // 0..124
    const int row_base = by * 128;

    const __half* Ap0 = &A[(size_t)(row_base + a_row0) * K + a_col];
    const __half* Ap1 = &A[(size_t)(row_base + a_row0 + 64) * K + a_col];
    const float* Bp0 = &B[(size_t)b_row0 * N + bx * 128 + b_col];
    const float* Bp1 = &B[(size_t)(b_row0 + 8) * N + bx * 128 + b_col];

    uint2 aR0 = *(const uint2*)Ap0;
    uint2 aR1 = *(const uint2*)Ap1;
    float4 bR0 = *(const float4*)Bp0;
    float4 bR1 = *(const float4*)Bp1;
    float4 sc = *(const float4*)&g_bn_scale[a_col];
    float4 sh = *(const float4*)&g_bn_shift[a_col];

    for (int k0 = 0; k0 < K; k0 += 16) {
        {
            float2 h0 = __half22float2(*(__half2*)&aR0.x);
            float2 h1 = __half22float2(*(__half2*)&aR0.y);
            As[a_col + 0][a_row0] = f2tf32(fmaxf(h0.x * sc.x + sh.x, 0.f));
            As[a_col + 1][a_row0] = f2tf32(fmaxf(h0.y * sc.y + sh.y, 0.f));
            As[a_col + 2][a_row0] = f2tf32(fmaxf(h1.x * sc.z + sh.z, 0.f));
            As[a_col + 3][a_row0] = f2tf32(fmaxf(h1.y * sc.w + sh.w, 0.f));
            float2 g0 = __half22float2(*(__half2*)&aR1.x);
            float2 g1 = __half22float2(*(__half2*)&aR1.y);
            As[a_col + 0][a_row0 + 64] = f2tf32(fmaxf(g0.x * sc.x + sh.x, 0.f));
            As[a_col + 1][a_row0 + 64] = f2tf32(fmaxf(g0.y * sc.y + sh.y, 0.f));
            As[a_col + 2][a_row0 + 64] = f2tf32(fmaxf(g1.x * sc.z + sh.z, 0.f));
            As[a_col + 3][a_row0 + 64] = f2tf32(fmaxf(g1.y * sc.w + sh.w, 0.f));
            *(uint4*)&Bs[b_row0][b_col] =
                make_uint4(f2tf32(bR0.x), f2tf32(bR0.y), f2tf32(bR0.z), f2tf32(bR0.w));
            *(uint4*)&Bs[b_row0 + 8][b_col] =
                make_uint4(f2tf32(bR1.x), f2tf32(bR1.y), f2tf32(bR1.z), f2tf32(bR1.w));
        }
        __syncthreads();
        if (k0 + 16 < K) {
            aR0 = *(const uint2*)(Ap0 + k0 + 16);
            aR1 = *(const uint2*)(Ap1 + k0 + 16);
            bR0 = *(const float4*)(Bp0 + (size_t)(k0 + 16) * N);
            bR1 = *(const float4*)(Bp1 + (size_t)(k0 + 16) * N);
            sc = *(const float4*)&g_bn_scale[k0 + 16 + a_col];
            sh = *(const float4*)&g_bn_shift[k0 + 16 + a_col];
        }
#pragma unroll
        for (int ks = 0; ks < 16; ks += 8) {
            unsigned af[2][4];
#pragma unroll
            for (int mi = 0; mi < 2; mi++) {
                int m0 = wm + mi * 16 + g;
                af[mi][0] = As[ks + tig][m0];
                af[mi][1] = As[ks + tig][m0 + 8];
                af[mi][2] = As[ks + tig + 4][m0];
                af[mi][3] = As[ks + tig + 4][m0 + 8];
            }
            unsigned bf[8][2];
#pragma unroll
            for (int nj = 0; nj < 8; nj++) {
                int n0 = wn + nj * 8 + g;
                bf[nj][0] = Bs[ks + tig][n0];
                bf[nj][1] = Bs[ks + tig + 4][n0];
            }
#pragma unroll
            for (int mi = 0; mi < 2; mi++)
#pragma unroll
                for (int nj = 0; nj < 8; nj++) {
                    asm volatile(
                        "mma.sync.aligned.m16n8k8.row.col.f32.tf32.tf32.f32 "
                        "{%0,%1,%2,%3}, {%4,%5,%6,%7}, {%8,%9}, {%0,%1,%2,%3};\n"
                        : "+f"(c[mi][nj][0]), "+f"(c[mi][nj][1]),
                          "+f"(c[mi][nj][2]), "+f"(c[mi][nj][3])
                        : "r"(af[mi][0]), "r"(af[mi][1]), "r"(af[mi][2]), "r"(af[mi][3]),
                          "r"(bf[nj][0]), "r"(bf[nj][1]));
                }
        }
        __syncthreads();
    }

    // epilogue: store C (fp16) + per-head attention projections from fragments
#pragma unroll
    for (int mi = 0; mi < 2; mi++) {
#pragma unroll
        for (int part = 0; part < 2; part++) {
            int r = row_base + wm + mi * 16 + g + part * 8;
            float ps0 = 0.f, ps1 = 0.f, pd0 = 0.f, pd1 = 0.f;
#pragma unroll
            for (int nj = 0; nj < 8; nj++) {
                int cb = bx * 128 + wn + nj * 8 + tig * 2;
                float v0 = c[mi][nj][part * 2];
                float v1 = c[mi][nj][part * 2 + 1];
                *(__half2*)&Cc[(size_t)r * N + cb] = __floats2half2_rn(v0, v1);
                float s0 = a_s[cb], s1 = a_s[cb + 1];
                float d0 = a_d[cb], d1 = a_d[cb + 1];
                if (CH == 32 && nj >= 4) {
                    ps1 += v0 * s0 + v1 * s1;
                    pd1 += v0 * d0 + v1 * d1;
                } else {
                    ps0 += v0 * s0 + v1 * s1;
                    pd0 += v0 * d0 + v1 * d1;
                }
            }
            ps0 += __shfl_xor_sync(0xffffffffu, ps0, 1);
            ps0 += __shfl_xor_sync(0xffffffffu, ps0, 2);
            pd0 += __shfl_xor_sync(0xffffffffu, pd0, 1);
            pd0 += __shfl_xor_sync(0xffffffffu, pd0, 2);
            if (CH == 32) {
                ps1 += __shfl_xor_sync(0xffffffffu, ps1, 1);
                ps1 += __shfl_xor_sync(0xffffffffu, ps1, 2);
                pd1 += __shfl_xor_sync(0xffffffffu, pd1, 1);
                pd1 += __shfl_xor_sync(0xffffffffu, pd1, 2);
            }
            if (tig == 0) {
                if (CH == 64) {
                    int head = (bx * 128 + wn) / 64;
                    g_als[(size_t)r * 8 + head] = ps0;
                    g_ald[(size_t)r * 8 + head] = pd0;
                } else {
                    int head0 = (bx * 128 + wn) / 32;
                    g_als[(size_t)r * 8 + head0] = ps0;
                    g_ald[(size_t)r * 8 + head0] = pd0;
                    g_als[(size_t)r * 8 + head0 + 1] = ps1;
                    g_ald[(size_t)r * 8 + head0 + 1] = pd1;
                }
            }
        }
    }
}

// ---------------- fully fused GAT aggregation: WPN warps per node, batched loads ----
template <int HC, int WPN>
__global__ __launch_bounds__(256) void gat_gather(const __half* __restrict__ h,
                                                  __half* __restrict__ outp, int Nn) {
    constexpr int C = HC / 8;           // channels per head
    constexpr int CW = HC / WPN;        // channels per warp
    constexpr int V = CW / 128;         // 4-channel chunks per lane (1 or 2)
    constexpr int U = (V == 1) ? 8 : 4; // edge batch size
    int warpGlobal = (blockIdx.x * blockDim.x + threadIdx.x) >> 5;
    int n = warpGlobal / WPN;
    int part = warpGlobal - n * WPN;
    if (n >= Nn) return;
    int lane = threadIdx.x & 31;
    int beg = g_row_ptr[n], end = g_row_ptr[n + 1];
    int deg = end - beg;
    int total = deg + 1;
    const int cbase = part * CW + lane * 4;

    int head[V];
    float ald[V];
#pragma unroll
    for (int v = 0; v < V; v++) {
        head[v] = (cbase + v * 128) / C;
        ald[v] = g_ald[(size_t)n * 8 + head[v]];
    }

    float4 acc[V];
    float ssum[V];
#pragma unroll
    for (int v = 0; v < V; v++) {
        acc[v] = make_float4(0.f, 0.f, 0.f, 0.f);
        ssum[v] = 0.f;
    }

    int i = 0;
    for (; i + U <= total; i += U) {
        int s[U];
#pragma unroll
        for (int j = 0; j < U; j++) {
            int e = i + j;
            s[j] = (e < deg) ? g_col[beg + e] : n;
        }
        float alv[U][V];
        uint2 hr[U][V];
#pragma unroll
        for (int j = 0; j < U; j++) {
            const __half* hp = h + (size_t)s[j] * HC + cbase;
            const float* ap = &g_als[(size_t)s[j] * 8];
#pragma unroll
            for (int v = 0; v < V; v++) {
                alv[j][v] = ap[head[v]];
                hr[j][v] = *(const uint2*)(hp + v * 128);
            }
        }
#pragma unroll
        for (int j = 0; j < U; j++) {
#pragma unroll
            for (int v = 0; v < V; v++) {
                float al = alv[j][v] + ald[v];
                al = (al > 0.f) ? al : 0.2f * al;
                float e = __expf(fminf(al, 80.f));
                ssum[v] += e;
                float2 a0 = __half22float2(*(__half2*)&hr[j][v].x);
                float2 a1 = __half22float2(*(__half2*)&hr[j][v].y);
                acc[v].x += e * a0.x;
                acc[v].y += e * a0.y;
                acc[v].z += e * a1.x;
                acc[v].w += e * a1.y;
            }
        }
    }
    for (; i < total; i++) {
        int s0 = (i < deg) ? g_col[beg + i] : n;
        const __half* hp = h + (size_t)s0 * HC + cbase;
        const float* ap = &g_als[(size_t)s0 * 8];
#pragma unroll
        for (int v = 0; v < V; v++) {
            float al = ap[head[v]] + ald[v];
            al = (al > 0.f) ? al : 0.2f * al;
            float e = __expf(fminf(al, 80.f));
            ssum[v] += e;
            uint2 r = *(const uint2*)(hp + v * 128);
            float2 a0 = __half22float2(*(__half2*)&r.x);
            float2 a1 = __half22float2(*(__half2*)&r.y);
            acc[v].x += e * a0.x;
            acc[v].y += e * a0.y;
            acc[v].z += e * a1.x;
            acc[v].w += e * a1.y;
        }
    }
#pragma unroll
    for (int v = 0; v < V; v++) {
        float dinv = 1.0f / (ssum[v] + 1e-16f);
        __half2 o0 = __floats2half2_rn(acc[v].x * dinv, acc[v].y * dinv);
        __half2 o1 = __floats2half2_rn(acc[v].z * dinv, acc[v].w * dinv);
        *(uint2*)&outp[(size_t)n * HC + cbase + v * 128] =
            make_uint2(h2u(o0), h2u(o1));
    }
}

// ---------------- BatchNorm stats (fp16 input): partial sums, no atomics ------------
__global__ void bn_stats(const __half* __restrict__ x, int Nn, int HC) {
    int c = blockIdx.x * blockDim.x + threadIdx.x;
    float s = 0.f, s2 = 0.f;
    for (int r = blockIdx.y; r < Nn; r += 128) {
        float v = __half2float(x[(size_t)r * HC + c]);
        s += v;
        s2 += v * v;
    }
    g_bn_part[blockIdx.y][c] = make_float2(s, s2);
}

// ---------------- layer-3 BN stats + raw per-graph extrema pool (single read) -------
// batch is sorted; strided rows are non-decreasing in graph id, so run-detection
// with flush-on-change gives exact per-graph max/min with few atomics.
__global__ void bn_stats_pool(const __half* __restrict__ x,
                              const int* __restrict__ batch, int Nn) {
    int c = blockIdx.x * blockDim.x + threadIdx.x;  // c < 512
    float s = 0.f, s2 = 0.f;
    float mx = 0.f, mn = 0.f;
    int cur = -1;
    for (int r = blockIdx.y; r < Nn; r += 128) {
        float v = __half2float(x[(size_t)r * 512 + c]);
        s += v;
        s2 += v * v;
        int b = batch[r];
        if (b != cur) {
            if (cur >= 0) {
                atomicMax(&g_pmax[cur * 512 + c], f2o(mx));
                atomicMin(&g_pmin[cur * 512 + c], f2o(mn));
            }
            cur = b;
            mx = v;
            mn = v;
        } else {
            mx = fmaxf(mx, v);
            mn = fminf(mn, v);
        }
    }
    if (cur >= 0) {
        atomicMax(&g_pmax[cur * 512 + c], f2o(mx));
        atomicMin(&g_pmin[cur * 512 + c], f2o(mn));
    }
    g_bn_part[blockIdx.y][c] = make_float2(s, s2);
}

__global__ void bn_finalize(const float* __restrict__ gam, const float* __restrict__ bet,
                            int HC, double invN) {
    int c = blockIdx.x * blockDim.x + threadIdx.x;
    if (c >= HC) return;
    double s = 0.0, s2 = 0.0;
    for (int y = 0; y < 128; y++) {
        float2 p = g_bn_part[y][c];
        s += (double)p.x;
        s2 += (double)p.y;
    }
    float mean = (float)(s * invN);
    float var = (float)(s2 * invN) - mean * mean;
    float rstd = rsqrtf(var + 1e-5f);
    float sc = gam[c] * rstd;
    g_bn_scale[c] = sc;
    g_bn_shift[c] = bet[c] - mean * sc;
}

// ---------------- FC head: applies layer-3 BN+ReLU to pooled raw extrema ------------
__global__ void fc_kernel(const float* __restrict__ fcW, const float* __restrict__ fcb,
                          float* __restrict__ outp) {
    int tid = blockIdx.x * blockDim.x + threadIdx.x;
    if (tid >= 160) return;
    int b = tid / 10, o = tid % 10;
    float s = fcb[o];
    for (int k = 0; k < 512; k++) {
        float sc = g_bn_scale[k], sh = g_bn_shift[k];
        float ext = (sc >= 0.f) ? o2f(g_pmax[b * 512 + k]) : o2f(g_pmin[b * 512 + k]);
        float pooled = fmaxf(sc * ext + sh, 0.f);
        s += pooled * fcW[k * 10 + o];
    }
    outp[b * 10 + o] = s;
}

// ---------------- launch (single stream — multi-stream capture regressed in R13) ----
extern "C" void kernel_launch(void* const* d_in, const int* in_sizes, int n_in,
                              void* d_out, int out_size) {
    const float* x   = (const float*)d_in[0];
    const int*   ei  = (const int*)d_in[1];
    const int*   batch = (const int*)d_in[2];
    const float* W1  = (const float*)d_in[3];
    const float* as1 = (const float*)d_in[4];
    const float* ad1 = (const float*)d_in[5];
    const float* g1  = (const float*)d_in[7];
    const float* be1 = (const float*)d_in[8];
    const float* W2  = (const float*)d_in[9];
    const float* as2 = (const float*)d_in[10];
    const float* ad2 = (const float*)d_in[11];
    const float* g2  = (const float*)d_in[13];
    const float* be2 = (const float*)d_in[14];
    const float* W3  = (const float*)d_in[15];
    const float* as3 = (const float*)d_in[16];
    const float* ad3 = (const float*)d_in[17];
    const float* g3  = (const float*)d_in[19];
    const float* be3 = (const float*)d_in[20];
    const float* fcW = (const float*)d_in[21];
    const float* fcb = (const float*)d_in[22];
    float* out = (float*)d_out;

    int N = in_sizes[0] / 3;
    int E = in_sizes[1] / 2;

    __half *bufH, *bufX;
    cudaGetSymbolAddress((void**)&bufH, g_h);
    cudaGetSymbolAddress((void**)&bufX, g_x);

    double invN = 1.0 / (double)N;
    int gy = (N + 127) / 128;
    int gb1 = (N + 7) / 8;          // WPN=1: 8 nodes per 256-thread block
    int gb2 = (N * 2 + 7) / 8;      // WPN=2: 4 nodes per block

    int zn = (N > 8192) ? N : 8192;
    zero_init<<<(zn + 255) / 256, 256>>>(N);
    hist_kernel<<<(E + 255) / 256, 256>>>(ei, E);
    scan_kernel<<<1, 1024>>>(N);
    scatter_kernel<<<(E + 255) / 256, 256>>>(ei, E);

    // ---- layer 1 ----
    gemm_l1_fused<<<(N + 3) / 4, 128>>>(x, W1, as1, ad1, bufH, N);
    gat_gather<128, 1><<<gb1, 256>>>(bufH, bufX, N);
    bn_stats<<<dim3(1, 128), 128>>>(bufX, N, 128);
    bn_finalize<<<1, 128>>>(g1, be1, 128, invN);

    // ---- layer 2 ---- (BN of layer-1 output fused into A-load; al fused in epilogue)
    gemm_tf32<32><<<dim3(2, gy), 256>>>(bufX, W2, bufH, as2, ad2, 256, 128);
    gat_gather<256, 2><<<gb2, 256>>>(bufH, bufX, N);
    bn_stats<<<dim3(2, 128), 128>>>(bufX, N, 256);
    bn_finalize<<<1, 256>>>(g2, be2, 256, invN);

    // ---- layer 3 ---- (pool extrema fused into the BN stats read)
    gemm_tf32<64><<<dim3(4, gy), 256>>>(bufX, W3, bufH, as3, ad3, 512, 256);
    gat_gather<512, 2><<<gb2, 256>>>(bufH, bufX, N);
    bn_stats_pool<<<dim3(4, 128), 128>>>(bufX, batch, N);
    bn_finalize<<<2, 256>>>(g3, be3, 512, invN);

    // ---- fc (BN+ReLU applied to pooled raw extrema) ----
    fc_kernel<<<1, 192>>>(fcW, fcb, out);
}

// round 15
// speedup vs baseline: 1.2227x; 1.2227x over previous
#include <cuda_runtime.h>
#include <cuda_fp16.h>
#include <math.h>

#define NMAX 20000
#define NPAD 20128      // NMAX rounded up past 157*128, removes GEMM bound checks
#define EMAX 320000

// ---------------- device scratch (static, no allocations) ----------------
__device__ __half g_h[NPAD * 512];      // GEMM outputs (gather input), fp16
__device__ __half g_x[NPAD * 512];      // gather outputs (GEMM A / BN / pool input), fp16
__device__ float  g_als[NPAD * 8];
__device__ float  g_ald[NPAD * 8];
__device__ int    g_counts[NMAX];
__device__ int    g_offs[NMAX];
__device__ int    g_row_ptr[NMAX + 1];
__device__ int    g_col[EMAX];
__device__ float2 g_bn_part[128][512];
__device__ float  g_bn_scale[512];
__device__ float  g_bn_shift[512];
__device__ int    g_pooled[16 * 512];   // float bits, values >= 0 so int atomicMax works

__device__ __forceinline__ unsigned h2u(__half2 h) {
    return *reinterpret_cast<unsigned*>(&h);
}
__device__ __forceinline__ unsigned f2tf32(float f) {
    unsigned u;
    asm("cvt.rna.tf32.f32 %0, %1;" : "=r"(u) : "f"(f));
    return u;
}

// ---------------- small utility kernels ----------------
__global__ void zero_init(int Nn) {
    int i = blockIdx.x * blockDim.x + threadIdx.x;
    if (i < Nn) g_counts[i] = 0;
    if (i < 16 * 512) g_pooled[i] = 0;
}

__global__ void hist_kernel(const int* __restrict__ ei, int E) {
    int e = blockIdx.x * blockDim.x + threadIdx.x;
    if (e < E) atomicAdd(&g_counts[ei[E + e]], 1);
}

__global__ void scan_kernel(int Nn) {
    __shared__ int sh[1024];
    int tid = threadIdx.x;
    int per = (Nn + 1023) / 1024;
    int start = tid * per;
    int s = 0;
    for (int i = 0; i < per; i++) {
        int idx = start + i;
        if (idx < Nn) s += g_counts[idx];
    }
    sh[tid] = s;
    __syncthreads();
    for (int off = 1; off < 1024; off <<= 1) {
        int v = 0;
        if (tid >= off) v = sh[tid - off];
        __syncthreads();
        sh[tid] += v;
        __syncthreads();
    }
    int run = sh[tid] - s;  // exclusive
    for (int i = 0; i < per; i++) {
        int idx = start + i;
        if (idx < Nn) {
            g_row_ptr[idx] = run;
            g_offs[idx] = run;
            run += g_counts[idx];
        }
    }
    if (tid == 1023) g_row_ptr[Nn] = sh[1023];
}

__global__ void scatter_kernel(const int* __restrict__ ei, int E) {
    int e = blockIdx.x * blockDim.x + threadIdx.x;
    if (e < E) {
        int s = ei[e];
        int d = ei[E + e];
        int pos = atomicAdd(&g_offs[d], 1);
        g_col[pos] = s;
    }
}

// ---------------- layer-1: GEMM (K=3) fused with attention projections ----------------
__global__ __launch_bounds__(128) void gemm_l1_fused(const float* __restrict__ x,
                                                     const float* __restrict__ W,
                                                     const float* __restrict__ a_s,
                                                     const float* __restrict__ a_d,
                                                     __half* __restrict__ outp, int Nn) {
    int warp = threadIdx.x >> 5;
    int lane = threadIdx.x & 31;
    int n = blockIdx.x * 4 + warp;
    if (n >= Nn) return;
    float x0 = x[n * 3 + 0], x1 = x[n * 3 + 1], x2 = x[n * 3 + 2];
    int c = lane * 4;
    float4 w0 = *(const float4*)&W[c];
    float4 w1 = *(const float4*)&W[128 + c];
    float4 w2 = *(const float4*)&W[256 + c];
    float4 v;
    v.x = x0 * w0.x + x1 * w1.x + x2 * w2.x;
    v.y = x0 * w0.y + x1 * w1.y + x2 * w2.y;
    v.z = x0 * w0.z + x1 * w1.z + x2 * w2.z;
    v.w = x0 * w0.w + x1 * w1.w + x2 * w2.w;
    __half2 p0 = __floats2half2_rn(v.x, v.y);
    __half2 p1 = __floats2half2_rn(v.z, v.w);
    *(uint2*)&outp[(size_t)n * 128 + c] = make_uint2(h2u(p0), h2u(p1));
    float4 s4 = *(const float4*)&a_s[c];
    float4 d4 = *(const float4*)&a_d[c];
    float ps = v.x * s4.x + v.y * s4.y + v.z * s4.z + v.w * s4.w;
    float pd = v.x * d4.x + v.y * d4.y + v.z * d4.z + v.w * d4.w;
    ps += __shfl_xor_sync(0xffffffffu, ps, 2);
    ps += __shfl_xor_sync(0xffffffffu, ps, 1);
    pd += __shfl_xor_sync(0xffffffffu, pd, 2);
    pd += __shfl_xor_sync(0xffffffffu, pd, 1);
    if ((lane & 3) == 0) {
        int hh = lane >> 2;
        g_als[n * 8 + hh] = ps;
        g_ald[n * 8 + hh] = pd;
    }
}

// ---------------- pipelined tf32 tensor-core GEMM: C(fp16) = relu(BN(A(fp16))) @ B ---
template <int CH>
__global__ __launch_bounds__(256, 2) void gemm_tf32(const __half* __restrict__ A,
                                                    const float* __restrict__ B,
                                                    __half* __restrict__ Cc,
                                                    const float* __restrict__ a_s,
                                                    const float* __restrict__ a_d,
                                                    int N, int K) {
    __shared__ unsigned As[16][136];   // [k][m], tf32 bits
    __shared__ unsigned Bs[16][136];   // [k][n], tf32 bits
    int tid = threadIdx.x;
    int bx = blockIdx.x, by = blockIdx.y;
    int lane = tid & 31;
    int g = lane >> 2;         // groupID (0..7)
    int tig = lane & 3;        // thread in group (0..3)
    int warp = tid >> 5;
    int wm = (warp & 3) * 32;  // warp M offset within block tile
    int wn = (warp >> 2) * 64; // warp N offset within block tile

    float c[2][8][4];
#pragma unroll
    for (int mi = 0; mi < 2; mi++)
#pragma unroll
        for (int nj = 0; nj < 8; nj++)
#pragma unroll
            for (int q = 0; q < 4; q++) c[mi][nj][q] = 0.f;

    int a_row0 = tid >> 2;          // 0..63
    int a_col = (tid & 3) << 2;     // 0,4,8,12
    int b_row0 = tid >> 5;          // 0..7
    int b_col = (tid & 31) << 2;    // 0..124
    const int row_base = by * 128;

    const __half* Ap0 = &A[(size_t)(row_base + a_row0) * K + a_col];
    const __half* Ap1 = &A[(size_t)(row_base + a_row0 + 64) * K + a_col];
    const float* Bp0 = &B[(size_t)b_row0 * N + bx * 128 + b_col];
    const float* Bp1 = &B[(size_t)(b_row0 + 8) * N + bx * 128 + b_col];

    uint2 aR0 = *(const uint2*)Ap0;
    uint2 aR1 = *(const uint2*)Ap1;
    float4 bR0 = *(const float4*)Bp0;
    float4 bR1 = *(const float4*)Bp1;
    float4 sc = *(const float4*)&g_bn_scale[a_col];
    float4 sh = *(const float4*)&g_bn_shift[a_col];

    for (int k0 = 0; k0 < K; k0 += 16) {
        {
            float2 h0 = __half22float2(*(__half2*)&aR0.x);
            float2 h1 = __half22float2(*(__half2*)&aR0.y);
            As[a_col + 0][a_row0] = f2tf32(fmaxf(h0.x * sc.x + sh.x, 0.f));
            As[a_col + 1][a_row0] = f2tf32(fmaxf(h0.y * sc.y + sh.y, 0.f));
            As[a_col + 2][a_row0] = f2tf32(fmaxf(h1.x * sc.z + sh.z, 0.f));
            As[a_col + 3][a_row0] = f2tf32(fmaxf(h1.y * sc.w + sh.w, 0.f));
            float2 g0 = __half22float2(*(__half2*)&aR1.x);
            float2 g1 = __half22float2(*(__half2*)&aR1.y);
            As[a_col + 0][a_row0 + 64] = f2tf32(fmaxf(g0.x * sc.x + sh.x, 0.f));
            As[a_col + 1][a_row0 + 64] = f2tf32(fmaxf(g0.y * sc.y + sh.y, 0.f));
            As[a_col + 2][a_row0 + 64] = f2tf32(fmaxf(g1.x * sc.z + sh.z, 0.f));
            As[a_col + 3][a_row0 + 64] = f2tf32(fmaxf(g1.y * sc.w + sh.w, 0.f));
            *(uint4*)&Bs[b_row0][b_col] =
                make_uint4(f2tf32(bR0.x), f2tf32(bR0.y), f2tf32(bR0.z), f2tf32(bR0.w));
            *(uint4*)&Bs[b_row0 + 8][b_col] =
                make_uint4(f2tf32(bR1.x), f2tf32(bR1.y), f2tf32(bR1.z), f2tf32(bR1.w));
        }
        __syncthreads();
        if (k0 + 16 < K) {
            aR0 = *(const uint2*)(Ap0 + k0 + 16);
            aR1 = *(const uint2*)(Ap1 + k0 + 16);
            bR0 = *(const float4*)(Bp0 + (size_t)(k0 + 16) * N);
            bR1 = *(const float4*)(Bp1 + (size_t)(k0 + 16) * N);
            sc = *(const float4*)&g_bn_scale[k0 + 16 + a_col];
            sh = *(const float4*)&g_bn_shift[k0 + 16 + a_col];
        }
#pragma unroll
        for (int ks = 0; ks < 16; ks += 8) {
            unsigned af[2][4];
#pragma unroll
            for (int mi = 0; mi < 2; mi++) {
                int m0 = wm + mi * 16 + g;
                af[mi][0] = As[ks + tig][m0];
                af[mi][1] = As[ks + tig][m0 + 8];
                af[mi][2] = As[ks + tig + 4][m0];
                af[mi][3] = As[ks + tig + 4][m0 + 8];
            }
            unsigned bf[8][2];
#pragma unroll
            for (int nj = 0; nj < 8; nj++) {
                int n0 = wn + nj * 8 + g;
                bf[nj][0] = Bs[ks + tig][n0];
                bf[nj][1] = Bs[ks + tig + 4][n0];
            }
#pragma unroll
            for (int mi = 0; mi < 2; mi++)
#pragma unroll
                for (int nj = 0; nj < 8; nj++) {
                    asm volatile(
                        "mma.sync.aligned.m16n8k8.row.col.f32.tf32.tf32.f32 "
                        "{%0,%1,%2,%3}, {%4,%5,%6,%7}, {%8,%9}, {%0,%1,%2,%3};\n"
                        : "+f"(c[mi][nj][0]), "+f"(c[mi][nj][1]),
                          "+f"(c[mi][nj][2]), "+f"(c[mi][nj][3])
                        : "r"(af[mi][0]), "r"(af[mi][1]), "r"(af[mi][2]), "r"(af[mi][3]),
                          "r"(bf[nj][0]), "r"(bf[nj][1]));
                }
        }
        __syncthreads();
    }

    // epilogue: store C (fp16) + per-head attention projections from fragments
#pragma unroll
    for (int mi = 0; mi < 2; mi++) {
#pragma unroll
        for (int part = 0; part < 2; part++) {
            int r = row_base + wm + mi * 16 + g + part * 8;
            float ps0 = 0.f, ps1 = 0.f, pd0 = 0.f, pd1 = 0.f;
#pragma unroll
            for (int nj = 0; nj < 8; nj++) {
                int cb = bx * 128 + wn + nj * 8 + tig * 2;
                float v0 = c[mi][nj][part * 2];
                float v1 = c[mi][nj][part * 2 + 1];
                *(__half2*)&Cc[(size_t)r * N + cb] = __floats2half2_rn(v0, v1);
                float s0 = a_s[cb], s1 = a_s[cb + 1];
                float d0 = a_d[cb], d1 = a_d[cb + 1];
                if (CH == 32 && nj >= 4) {
                    ps1 += v0 * s0 + v1 * s1;
                    pd1 += v0 * d0 + v1 * d1;
                } else {
                    ps0 += v0 * s0 + v1 * s1;
                    pd0 += v0 * d0 + v1 * d1;
                }
            }
            ps0 += __shfl_xor_sync(0xffffffffu, ps0, 1);
            ps0 += __shfl_xor_sync(0xffffffffu, ps0, 2);
            pd0 += __shfl_xor_sync(0xffffffffu, pd0, 1);
            pd0 += __shfl_xor_sync(0xffffffffu, pd0, 2);
            if (CH == 32) {
                ps1 += __shfl_xor_sync(0xffffffffu, ps1, 1);
                ps1 += __shfl_xor_sync(0xffffffffu, ps1, 2);
                pd1 += __shfl_xor_sync(0xffffffffu, pd1, 1);
                pd1 += __shfl_xor_sync(0xffffffffu, pd1, 2);
            }
            if (tig == 0) {
                if (CH == 64) {
                    int head = (bx * 128 + wn) / 64;
                    g_als[(size_t)r * 8 + head] = ps0;
                    g_ald[(size_t)r * 8 + head] = pd0;
                } else {
                    int head0 = (bx * 128 + wn) / 32;
                    g_als[(size_t)r * 8 + head0] = ps0;
                    g_ald[(size_t)r * 8 + head0] = pd0;
                    g_als[(size_t)r * 8 + head0 + 1] = ps1;
                    g_ald[(size_t)r * 8 + head0 + 1] = pd1;
                }
            }
        }
    }
}

// ---------------- fully fused GAT aggregation: WPN warps per node, batched loads ----
template <int HC, int WPN>
__global__ __launch_bounds__(256) void gat_gather(const __half* __restrict__ h,
                                                  __half* __restrict__ outp, int Nn) {
    constexpr int C = HC / 8;           // channels per head
    constexpr int CW = HC / WPN;        // channels per warp
    constexpr int V = CW / 128;         // 4-channel chunks per lane (1 or 2)
    constexpr int U = (V == 1) ? 8 : 4; // edge batch size
    int warpGlobal = (blockIdx.x * blockDim.x + threadIdx.x) >> 5;
    int n = warpGlobal / WPN;
    int part = warpGlobal - n * WPN;
    if (n >= Nn) return;
    int lane = threadIdx.x & 31;
    int beg = g_row_ptr[n], end = g_row_ptr[n + 1];
    int deg = end - beg;
    int total = deg + 1;
    const int cbase = part * CW + lane * 4;

    int head[V];
    float ald[V];
#pragma unroll
    for (int v = 0; v < V; v++) {
        head[v] = (cbase + v * 128) / C;
        ald[v] = g_ald[(size_t)n * 8 + head[v]];
    }

    float4 acc[V];
    float ssum[V];
#pragma unroll
    for (int v = 0; v < V; v++) {
        acc[v] = make_float4(0.f, 0.f, 0.f, 0.f);
        ssum[v] = 0.f;
    }

    int i = 0;
    for (; i + U <= total; i += U) {
        int s[U];
#pragma unroll
        for (int j = 0; j < U; j++) {
            int e = i + j;
            s[j] = (e < deg) ? g_col[beg + e] : n;
        }
        float alv[U][V];
        uint2 hr[U][V];
#pragma unroll
        for (int j = 0; j < U; j++) {
            const __half* hp = h + (size_t)s[j] * HC + cbase;
            const float* ap = &g_als[(size_t)s[j] * 8];
#pragma unroll
            for (int v = 0; v < V; v++) {
                alv[j][v] = ap[head[v]];
                hr[j][v] = *(const uint2*)(hp + v * 128);
            }
        }
#pragma unroll
        for (int j = 0; j < U; j++) {
#pragma unroll
            for (int v = 0; v < V; v++) {
                float al = alv[j][v] + ald[v];
                al = (al > 0.f) ? al : 0.2f * al;
                float e = __expf(fminf(al, 80.f));
                ssum[v] += e;
                float2 a0 = __half22float2(*(__half2*)&hr[j][v].x);
                float2 a1 = __half22float2(*(__half2*)&hr[j][v].y);
                acc[v].x += e * a0.x;
                acc[v].y += e * a0.y;
                acc[v].z += e * a1.x;
                acc[v].w += e * a1.y;
            }
        }
    }
    for (; i < total; i++) {
        int s0 = (i < deg) ? g_col[beg + i] : n;
        const __half* hp = h + (size_t)s0 * HC + cbase;
        const float* ap = &g_als[(size_t)s0 * 8];
#pragma unroll
        for (int v = 0; v < V; v++) {
            float al = ap[head[v]] + ald[v];
            al = (al > 0.f) ? al : 0.2f * al;
            float e = __expf(fminf(al, 80.f));
            ssum[v] += e;
            uint2 r = *(const uint2*)(hp + v * 128);
            float2 a0 = __half22float2(*(__half2*)&r.x);
            float2 a1 = __half22float2(*(__half2*)&r.y);
            acc[v].x += e * a0.x;
            acc[v].y += e * a0.y;
            acc[v].z += e * a1.x;
            acc[v].w += e * a1.y;
        }
    }
#pragma unroll
    for (int v = 0; v < V; v++) {
        float dinv = 1.0f / (ssum[v] + 1e-16f);
        __half2 o0 = __floats2half2_rn(acc[v].x * dinv, acc[v].y * dinv);
        __half2 o1 = __floats2half2_rn(acc[v].z * dinv, acc[v].w * dinv);
        *(uint2*)&outp[(size_t)n * HC + cbase + v * 128] =
            make_uint2(h2u(o0), h2u(o1));
    }
}

// ---------------- BatchNorm stats (fp16 input): partial sums, no atomics ------------
// NOTE: keep this loop branch-free — a data-dependent branch here serializes the
// strided loads and cost +80us in R13/R14.
__global__ void bn_stats(const __half* __restrict__ x, int Nn, int HC) {
    int c = blockIdx.x * blockDim.x + threadIdx.x;
    float s = 0.f, s2 = 0.f;
    for (int r = blockIdx.y; r < Nn; r += 128) {
        float v = __half2float(x[(size_t)r * HC + c]);
        s += v;
        s2 += v * v;
    }
    g_bn_part[blockIdx.y][c] = make_float2(s, s2);
}

__global__ void bn_finalize(const float* __restrict__ gam, const float* __restrict__ bet,
                            int HC, double invN) {
    int c = blockIdx.x * blockDim.x + threadIdx.x;
    if (c >= HC) return;
    double s = 0.0, s2 = 0.0;
    for (int y = 0; y < 128; y++) {
        float2 p = g_bn_part[y][c];
        s += (double)p.x;
        s2 += (double)p.y;
    }
    float mean = (float)(s * invN);
    float var = (float)(s2 * invN) - mean * mean;
    float rstd = rsqrtf(var + 1e-5f);
    float sc = gam[c] * rstd;
    g_bn_scale[c] = sc;
    g_bn_shift[c] = bet[c] - mean * sc;
}

// ---------------- global max pool with fused BN+ReLU (batch is sorted) -------------
__global__ void pool_kernel(const __half* __restrict__ x, const int* __restrict__ batch,
                            int Nn, int chunk) {
    int c = blockIdx.x * 128 + threadIdx.x;  // c < 512
    int r0 = blockIdx.y * chunk;
    if (r0 >= Nn) return;
    int r1 = min(r0 + chunk, Nn);
    float sc = g_bn_scale[c], sh = g_bn_shift[c];
    int cur = batch[r0];
    float m = 0.f;  // ReLU output >= 0
    for (int r = r0; r < r1; r++) {
        int b = batch[r];
        if (b != cur) {
            atomicMax(&g_pooled[cur * 512 + c], __float_as_int(m));
            cur = b;
            m = 0.f;
        }
        float v = fmaxf(__half2float(x[(size_t)r * 512 + c]) * sc + sh, 0.f);
        m = fmaxf(m, v);
    }
    atomicMax(&g_pooled[cur * 512 + c], __float_as_int(m));
}

// ---------------- FC head ----------------
__global__ void fc_kernel(const float* __restrict__ fcW, const float* __restrict__ fcb,
                          float* __restrict__ outp) {
    int tid = blockIdx.x * blockDim.x + threadIdx.x;
    if (tid >= 160) return;
    int b = tid / 10, o = tid % 10;
    float s = fcb[o];
    for (int k = 0; k < 512; k++)
        s += __int_as_float(g_pooled[b * 512 + k]) * fcW[k * 10 + o];
    outp[b * 10 + o] = s;
}

// ---------------- launch (single stream — multi-stream capture regressed in R13) ----
extern "C" void kernel_launch(void* const* d_in, const int* in_sizes, int n_in,
                              void* d_out, int out_size) {
    const float* x   = (const float*)d_in[0];
    const int*   ei  = (const int*)d_in[1];
    const int*   batch = (const int*)d_in[2];
    const float* W1  = (const float*)d_in[3];
    const float* as1 = (const float*)d_in[4];
    const float* ad1 = (const float*)d_in[5];
    const float* g1  = (const float*)d_in[7];
    const float* be1 = (const float*)d_in[8];
    const float* W2  = (const float*)d_in[9];
    const float* as2 = (const float*)d_in[10];
    const float* ad2 = (const float*)d_in[11];
    const float* g2  = (const float*)d_in[13];
    const float* be2 = (const float*)d_in[14];
    const float* W3  = (const float*)d_in[15];
    const float* as3 = (const float*)d_in[16];
    const float* ad3 = (const float*)d_in[17];
    const float* g3  = (const float*)d_in[19];
    const float* be3 = (const float*)d_in[20];
    const float* fcW = (const float*)d_in[21];
    const float* fcb = (const float*)d_in[22];
    float* out = (float*)d_out;

    int N = in_sizes[0] / 3;
    int E = in_sizes[1] / 2;

    __half *bufH, *bufX;
    cudaGetSymbolAddress((void**)&bufH, g_h);
    cudaGetSymbolAddress((void**)&bufX, g_x);

    double invN = 1.0 / (double)N;
    int gy = (N + 127) / 128;
    int gb1 = (N + 7) / 8;          // WPN=1: 8 nodes per 256-thread block
    int gb2 = (N * 2 + 7) / 8;      // WPN=2: 4 nodes per block
    int gb4 = (N * 4 + 7) / 8;      // WPN=4: 2 nodes per block

    int zn = (N > 8192) ? N : 8192;
    zero_init<<<(zn + 255) / 256, 256>>>(N);
    hist_kernel<<<(E + 255) / 256, 256>>>(ei, E);
    scan_kernel<<<1, 1024>>>(N);
    scatter_kernel<<<(E + 255) / 256, 256>>>(ei, E);

    // ---- layer 1 ----
    gemm_l1_fused<<<(N + 3) / 4, 128>>>(x, W1, as1, ad1, bufH, N);
    gat_gather<128, 1><<<gb1, 256>>>(bufH, bufX, N);
    bn_stats<<<dim3(1, 128), 128>>>(bufX, N, 128);
    bn_finalize<<<1, 128>>>(g1, be1, 128, invN);

    // ---- layer 2 ---- (BN of layer-1 output fused into A-load; al fused in epilogue)
    gemm_tf32<32><<<dim3(2, gy), 256>>>(bufX, W2, bufH, as2, ad2, 256, 128);
    gat_gather<256, 2><<<gb2, 256>>>(bufH, bufX, N);
    bn_stats<<<dim3(2, 128), 128>>>(bufX, N, 256);
    bn_finalize<<<1, 256>>>(g2, be2, 256, invN);

    // ---- layer 3 ---- (WPN=4: V=1, U=8 — max MLP, minimal registers)
    gemm_tf32<64><<<dim3(4, gy), 256>>>(bufX, W3, bufH, as3, ad3, 512, 256);
    gat_gather<512, 4><<<gb4, 256>>>(bufH, bufX, N);
    bn_stats<<<dim3(4, 128), 128>>>(bufX, N, 512);
    bn_finalize<<<2, 256>>>(g3, be3, 512, invN);

    // ---- pool (BN+ReLU fused) + fc ----
    int chunk = (N + 127) / 128;
    pool_kernel<<<dim3(4, 128), 128>>>(bufX, batch, N, chunk);
    fc_kernel<<<1, 192>>>(fcW, fcb, out);
}